// round 2
// baseline (speedup 1.0000x reference)
#include <cuda_runtime.h>

#define BB 16
#define CC 64
#define HH 64
#define WW 64
#define HW 4096

// scratch (static device allocations — allowed)
__device__ float g_off[BB * 18 * HW];      // offsets from offset conv
__device__ float g_s[BB * CC * HW];        // branch-sum feature map
__device__ float g_w1t[576 * 64];          // w1 repacked: [k*64+c][o]

// ---------------------------------------------------------------------------
// Kernel 1: offset conv — 3x3, pad 1, Cin=64, Cout=18, plus bias
// ---------------------------------------------------------------------------
__global__ __launch_bounds__(256) void offset_conv_kernel(
    const float* __restrict__ x, const float* __restrict__ w_off,
    const float* __restrict__ b_off)
{
    __shared__ float ws[18 * 64 * 9];     // 41.5 KB — whole w_off
    __shared__ float xs[4][18][19];

    int tid = threadIdx.x;
    int b   = blockIdx.y;
    int ty0 = (blockIdx.x >> 2) * 16;
    int tx0 = (blockIdx.x & 3) * 16;
    int ty  = tid >> 4, tx = tid & 15;

    for (int i = tid; i < 18 * 64 * 9; i += 256) ws[i] = w_off[i];

    float acc[18];
#pragma unroll
    for (int o = 0; o < 18; o++) acc[o] = 0.f;

    for (int cc0 = 0; cc0 < 64; cc0 += 4) {
        __syncthreads();
        for (int i = tid; i < 4 * 18 * 18; i += 256) {
            int c = i / 324, r = i % 324, yy = r / 18, xx = r % 18;
            int gy = ty0 - 1 + yy, gx = tx0 - 1 + xx;
            float v = 0.f;
            if (gy >= 0 && gy < 64 && gx >= 0 && gx < 64)
                v = x[((b * 64 + cc0 + c) * 64 + gy) * 64 + gx];
            xs[c][yy][xx] = v;
        }
        __syncthreads();
#pragma unroll
        for (int c = 0; c < 4; c++)
#pragma unroll
        for (int ky = 0; ky < 3; ky++)
#pragma unroll
        for (int kx = 0; kx < 3; kx++) {
            float xv = xs[c][ty + ky][tx + kx];
#pragma unroll
            for (int o = 0; o < 18; o++)
                acc[o] += ws[((o * 64 + cc0 + c) * 3 + ky) * 3 + kx] * xv;
        }
    }
    int ho = ty0 + ty, wo = tx0 + tx;
#pragma unroll
    for (int o = 0; o < 18; o++)
        g_off[((b * 18 + o) * 64 + ho) * 64 + wo] = acc[o] + b_off[o];
}

// ---------------------------------------------------------------------------
// Kernel 2: repack w1 [o][c][3][3] -> g_w1t[(k*64+c)*64 + o]
// ---------------------------------------------------------------------------
__global__ void repack_w1_kernel(const float* __restrict__ w1)
{
    int i = blockIdx.x * 256 + threadIdx.x;
    if (i < 36864) {
        int o = i / 576, r = i % 576, c = r / 9, k = r % 9;
        g_w1t[(k * 64 + c) * 64 + o] = w1[i];
    }
}

// ---------------------------------------------------------------------------
// Kernel 3: fused deformable conv (3x3, pad 1) + BN1 + ReLU -> g_s
// ---------------------------------------------------------------------------
__global__ __launch_bounds__(256) void deform_kernel(
    const float* __restrict__ x,
    const float* __restrict__ g1, const float* __restrict__ b1,
    const float* __restrict__ m1, const float* __restrict__ v1)
{
    __shared__ float val[576 * 16];    // 36,864 B, stride-16 rows
    __shared__ float wsh[32 * 64];     //  8,192 B
    __shared__ int   cpos[144];        // packed y0|x0<<6|y1<<12|x1<<18
    __shared__ float cw00[144], cw01[144], cw10[144], cw11[144];
    __shared__ float scale[64], bias[64];

    int tid = threadIdx.x;
    int wo0 = blockIdx.x * 16;
    int ho  = blockIdx.y;
    int b   = blockIdx.z;

    if (tid < 64) {
        float sc   = g1[tid] * rsqrtf(v1[tid] + 1e-5f);
        scale[tid] = sc;
        bias[tid]  = b1[tid] - m1[tid] * sc;
    }
    if (tid < 144) {
        int k = tid / 16, px = tid & 15;
        int ky = k / 3, kx = k % 3;
        int wo = wo0 + px;
        float dy = g_off[((b * 18 + 2 * k) * 64 + ho) * 64 + wo];
        float dx = g_off[((b * 18 + 2 * k + 1) * 64 + ho) * 64 + wo];
        float ys  = (float)(ho - 1 + ky) + dy;
        float xsm = (float)(wo - 1 + kx) + dx;
        float y0f = floorf(ys), x0f = floorf(xsm);
        float y1f = y0f + 1.f, x1f = x0f + 1.f;
        float wy1 = ys - y0f, wx1 = xsm - x0f;
        float wy0 = 1.f - wy1, wx0 = 1.f - wx1;
        bool vy0 = (y0f >= 0.f) && (y0f <= 63.f);
        bool vy1 = (y1f >= 0.f) && (y1f <= 63.f);
        bool vx0 = (x0f >= 0.f) && (x0f <= 63.f);
        bool vx1 = (x1f >= 0.f) && (x1f <= 63.f);
        cw00[tid] = (vy0 && vx0) ? wy0 * wx0 : 0.f;
        cw01[tid] = (vy0 && vx1) ? wy0 * wx1 : 0.f;
        cw10[tid] = (vy1 && vx0) ? wy1 * wx0 : 0.f;
        cw11[tid] = (vy1 && vx1) ? wy1 * wx1 : 0.f;
        // clamp EACH corner coordinate independently (bug fix vs round 1:
        // y1 must be clamp(y0f+1), not clamp(y0f)+1)
        int y0c = (int)fminf(fmaxf(y0f, 0.f), 63.f);
        int x0c = (int)fminf(fmaxf(x0f, 0.f), 63.f);
        int y1c = (int)fminf(fmaxf(y1f, 0.f), 63.f);
        int x1c = (int)fminf(fmaxf(x1f, 0.f), 63.f);
        cpos[tid] = y0c | (x0c << 6) | (y1c << 12) | (x1c << 18);
    }
    __syncthreads();

    // phase 1b: bilinear gather into SMEM columns
    for (int t = tid; t < 9216; t += 256) {
        int px = t & 15, c = (t >> 4) & 63, k = t >> 10;
        int pair = k * 16 + px;
        int p  = cpos[pair];
        int y0 = p & 63, x0 = (p >> 6) & 63;
        int y1 = (p >> 12) & 63, x1 = (p >> 18) & 63;
        const float* xb = x + (b * 64 + c) * HW;
        float v = cw00[pair] * xb[y0 * 64 + x0]
                + cw01[pair] * xb[y0 * 64 + x1]
                + cw10[pair] * xb[y1 * 64 + x0]
                + cw11[pair] * xb[y1 * 64 + x1];
        val[(k * 64 + c) * 16 + px] = v;
    }

    // phase 2: out[64][16] = w1t[64][576] * val[576][16]
    float acc0 = 0.f, acc1 = 0.f, acc2 = 0.f, acc3 = 0.f;
    int ty = tid >> 4, tx = tid & 15;
    for (int j = 0; j < 18; j++) {
        __syncthreads();
        for (int i = tid; i < 2048; i += 256)
            wsh[i] = g_w1t[j * 2048 + i];
        __syncthreads();
#pragma unroll 8
        for (int kcl = 0; kcl < 32; kcl++) {
            float4 wv = *(const float4*)&wsh[kcl * 64 + ty * 4];
            float  xv = val[(j * 32 + kcl) * 16 + tx];
            acc0 += wv.x * xv; acc1 += wv.y * xv;
            acc2 += wv.z * xv; acc3 += wv.w * xv;
        }
    }
    int wo = wo0 + tx;
    float a[4] = {acc0, acc1, acc2, acc3};
#pragma unroll
    for (int m = 0; m < 4; m++) {
        int oc = ty * 4 + m;
        float r = fmaxf(a[m] * scale[oc] + bias[oc], 0.f);
        g_s[((b * 64 + oc) * 64 + ho) * 64 + wo] = r;
    }
}

// ---------------------------------------------------------------------------
// Kernels 4/5: tiled direct conv, 64 outC x 16x16 pixel tile per block
// MODE 0: g_s += relu(bn(conv_KSZ(x)))           (5x5 branch)
// MODE 1: dst  = relu(bn(conv_KSZ(g_s)) + resid) (final 3x3 + identity)
// ---------------------------------------------------------------------------
template <int KSZ, int MODE>
__global__ __launch_bounds__(256, 2) void conv_tiled_kernel(
    const float* __restrict__ src, const float* __restrict__ w,
    const float* __restrict__ gg, const float* __restrict__ bbn,
    const float* __restrict__ mmn, const float* __restrict__ vvn,
    const float* __restrict__ resid, float* __restrict__ dst)
{
    constexpr int PAD = KSZ / 2;
    constexpr int XH  = 16 + KSZ - 1;
    constexpr int XW  = XH;
    constexpr int XWP = (XW & 1) ? XW : XW + 1;
    constexpr int KK  = KSZ * KSZ;

    __shared__ float xs[4][XH][XWP];
    __shared__ float wsm[4 * KK][64];
    __shared__ float scale[64], bias[64];

    int tid = threadIdx.x;
    int b   = blockIdx.y;
    int ty0 = (blockIdx.x >> 2) * 16;
    int tx0 = (blockIdx.x & 3) * 16;
    int ty  = tid >> 4, tx = tid & 15;

    if (tid < 64) {
        float sc   = gg[tid] * rsqrtf(vvn[tid] + 1e-5f);
        scale[tid] = sc;
        bias[tid]  = bbn[tid] - mmn[tid] * sc;
    }

    const float* in = (MODE == 0) ? src : (const float*)g_s;

    float acc[4][16];
#pragma unroll
    for (int m = 0; m < 4; m++)
#pragma unroll
        for (int n = 0; n < 16; n++) acc[m][n] = 0.f;

    for (int cc0 = 0; cc0 < 64; cc0 += 4) {
        __syncthreads();
        for (int i = tid; i < 4 * XH * XW; i += 256) {
            int c = i / (XH * XW), r = i % (XH * XW), yy = r / XW, xx = r % XW;
            int gy = ty0 - PAD + yy, gx = tx0 - PAD + xx;
            float v = 0.f;
            if (gy >= 0 && gy < 64 && gx >= 0 && gx < 64)
                v = in[((b * 64 + cc0 + c) * 64 + gy) * 64 + gx];
            xs[c][yy][xx] = v;
        }
        for (int i = tid; i < 64 * 4 * KK; i += 256) {
            int o = i / (4 * KK), r = i % (4 * KK), c = r / KK, kk = r % KK;
            wsm[c * KK + kk][o] = w[(o * 64 + cc0 + c) * KK + kk];
        }
        __syncthreads();
#pragma unroll
        for (int c = 0; c < 4; c++)
#pragma unroll
        for (int ky = 0; ky < KSZ; ky++) {
            float xrow[XW];
#pragma unroll
            for (int i2 = 0; i2 < XW; i2++) xrow[i2] = xs[c][tx + ky][i2];
#pragma unroll
            for (int kx = 0; kx < KSZ; kx++) {
                float4 wv = *(const float4*)&wsm[c * KK + ky * KSZ + kx][ty * 4];
#pragma unroll
                for (int n = 0; n < 16; n++) {
                    float xv = xrow[kx + n];
                    acc[0][n] += wv.x * xv;
                    acc[1][n] += wv.y * xv;
                    acc[2][n] += wv.z * xv;
                    acc[3][n] += wv.w * xv;
                }
            }
        }
    }

    int row = ty0 + tx;
#pragma unroll
    for (int m = 0; m < 4; m++) {
        int oc   = ty * 4 + m;
        int base = ((b * 64 + oc) * 64 + row) * 64 + tx0;
        float sc = scale[oc], bi = bias[oc];
#pragma unroll
        for (int n = 0; n < 16; n++) {
            float r = acc[m][n] * sc + bi;
            if (MODE == 0) {
                g_s[base + n] = fmaxf(r, 0.f) + g_s[base + n];
            } else {
                dst[base + n] = fmaxf(r + resid[base + n], 0.f);
            }
        }
    }
}

// ---------------------------------------------------------------------------
extern "C" void kernel_launch(void* const* d_in, const int* in_sizes, int n_in,
                              void* d_out, int out_size)
{
    const float* x     = (const float*)d_in[0];
    const float* w_off = (const float*)d_in[1];
    const float* b_off = (const float*)d_in[2];
    const float* w1    = (const float*)d_in[3];
    const float* g1    = (const float*)d_in[4];
    const float* b1    = (const float*)d_in[5];
    const float* m1    = (const float*)d_in[6];
    const float* v1    = (const float*)d_in[7];
    const float* w3    = (const float*)d_in[8];
    const float* g3    = (const float*)d_in[9];
    const float* b3    = (const float*)d_in[10];
    const float* m3    = (const float*)d_in[11];
    const float* v3    = (const float*)d_in[12];
    const float* w2    = (const float*)d_in[13];
    const float* g2    = (const float*)d_in[14];
    const float* b2    = (const float*)d_in[15];
    const float* m2    = (const float*)d_in[16];
    const float* v2    = (const float*)d_in[17];
    float* out = (float*)d_out;

    offset_conv_kernel<<<dim3(16, 16), 256>>>(x, w_off, b_off);
    repack_w1_kernel<<<144, 256>>>(w1);
    deform_kernel<<<dim3(4, 64, 16), 256>>>(x, g1, b1, m1, v1);
    conv_tiled_kernel<5, 0><<<dim3(16, 16), 256>>>(x, w3, g3, b3, m3, v3,
                                                   nullptr, nullptr);
    conv_tiled_kernel<3, 1><<<dim3(16, 16), 256>>>(nullptr, w2, g2, b2, m2, v2,
                                                   x, out);
}

// round 3
// speedup vs baseline: 1.0003x; 1.0003x over previous
#include <cuda_runtime.h>

#define BB 16
#define CC 64
#define HH 64
#define WW 64
#define HW 4096

typedef unsigned long long ull;

__device__ float g_off[BB * 18 * HW];      // offsets from offset conv
__device__ float g_s[BB * CC * HW];        // branch-sum feature map
__device__ float g_w1t[576 * 64];          // w1 repacked: [k*64+c][o]

// ---- f32x2 packed helpers ------------------------------------------------
__device__ __forceinline__ void ffma2(ull& d, ull a, ull b) {
    asm("fma.rn.f32x2 %0, %1, %2, %0;" : "+l"(d) : "l"(a), "l"(b));
}
__device__ __forceinline__ ull pack2(float lo, float hi) {
    ull r;
    asm("mov.b64 %0, {%1, %2};" : "=l"(r) : "f"(lo), "f"(hi));
    return r;
}
__device__ __forceinline__ float2 unpack2(ull v) {
    float2 r;
    asm("mov.b64 {%0, %1}, %2;" : "=f"(r.x), "=f"(r.y) : "l"(v));
    return r;
}

// ---------------------------------------------------------------------------
// Kernel 1: offset conv — 3x3, pad 1, Cin=64, Cout=18, plus bias
// weights repacked in SMEM to [tap(c,ky,kx)][o] so o-pairs are LDS.64
// ---------------------------------------------------------------------------
__global__ __launch_bounds__(256) void offset_conv_kernel(
    const float* __restrict__ x, const float* __restrict__ w_off,
    const float* __restrict__ b_off)
{
    __shared__ float ws[576 * 18];        // 41.5 KB, [tap][o]
    __shared__ float xs[4][18][19];

    int tid = threadIdx.x;
    int b   = blockIdx.y;
    int ty0 = (blockIdx.x >> 2) * 16;
    int tx0 = (blockIdx.x & 3) * 16;
    int ty  = tid >> 4, tx = tid & 15;

    for (int i = tid; i < 576 * 18; i += 256) {
        int tap = i / 18, o = i % 18;
        ws[i] = w_off[o * 576 + tap];
    }

    ull accp[9];
#pragma unroll
    for (int j = 0; j < 9; j++) accp[j] = 0ull;

    for (int cc0 = 0; cc0 < 64; cc0 += 4) {
        __syncthreads();
        for (int i = tid; i < 4 * 18 * 18; i += 256) {
            int c = i / 324, r = i % 324, yy = r / 18, xx = r % 18;
            int gy = ty0 - 1 + yy, gx = tx0 - 1 + xx;
            float v = 0.f;
            if (gy >= 0 && gy < 64 && gx >= 0 && gx < 64)
                v = x[((b * 64 + cc0 + c) * 64 + gy) * 64 + gx];
            xs[c][yy][xx] = v;
        }
        __syncthreads();
#pragma unroll
        for (int c = 0; c < 4; c++)
#pragma unroll
        for (int ky = 0; ky < 3; ky++)
#pragma unroll
        for (int kx = 0; kx < 3; kx++) {
            float xv = xs[c][ty + ky][tx + kx];
            ull xp = pack2(xv, xv);
            const float2* wp =
                (const float2*)&ws[(((cc0 + c) * 3 + ky) * 3 + kx) * 18];
#pragma unroll
            for (int j = 0; j < 9; j++) {
                float2 w2v = wp[j];
                ffma2(accp[j], pack2(w2v.x, w2v.y), xp);
            }
        }
    }
    int ho = ty0 + ty, wo = tx0 + tx;
#pragma unroll
    for (int j = 0; j < 9; j++) {
        float2 a = unpack2(accp[j]);
        g_off[((b * 18 + 2 * j) * 64 + ho) * 64 + wo]     = a.x + b_off[2 * j];
        g_off[((b * 18 + 2 * j + 1) * 64 + ho) * 64 + wo] = a.y + b_off[2 * j + 1];
    }
}

// ---------------------------------------------------------------------------
// Kernel 2: repack w1 [o][c][3][3] -> g_w1t[(k*64+c)*64 + o]
// ---------------------------------------------------------------------------
__global__ void repack_w1_kernel(const float* __restrict__ w1)
{
    int i = blockIdx.x * 256 + threadIdx.x;
    if (i < 36864) {
        int o = i / 576, r = i % 576, c = r / 9, k = r % 9;
        g_w1t[(k * 64 + c) * 64 + o] = w1[i];
    }
}

// ---------------------------------------------------------------------------
// Kernel 3: fused deformable conv (3x3, pad 1) + BN1 + ReLU -> g_s
// ---------------------------------------------------------------------------
__global__ __launch_bounds__(256) void deform_kernel(
    const float* __restrict__ x,
    const float* __restrict__ g1, const float* __restrict__ b1,
    const float* __restrict__ m1, const float* __restrict__ v1)
{
    __shared__ float val[576 * 16];    // stride-16 rows, conflict-free
    __shared__ float wsh[32 * 64];
    __shared__ int   cpos[144];
    __shared__ float cw00[144], cw01[144], cw10[144], cw11[144];
    __shared__ float scale[64], bias[64];

    int tid = threadIdx.x;
    int wo0 = blockIdx.x * 16;
    int ho  = blockIdx.y;
    int b   = blockIdx.z;

    if (tid < 64) {
        float sc   = g1[tid] * rsqrtf(v1[tid] + 1e-5f);
        scale[tid] = sc;
        bias[tid]  = b1[tid] - m1[tid] * sc;
    }
    if (tid < 144) {
        int k = tid / 16, px = tid & 15;
        int ky = k / 3, kx = k % 3;
        int wo = wo0 + px;
        float dy = g_off[((b * 18 + 2 * k) * 64 + ho) * 64 + wo];
        float dx = g_off[((b * 18 + 2 * k + 1) * 64 + ho) * 64 + wo];
        float ys  = (float)(ho - 1 + ky) + dy;
        float xsm = (float)(wo - 1 + kx) + dx;
        float y0f = floorf(ys), x0f = floorf(xsm);
        float y1f = y0f + 1.f, x1f = x0f + 1.f;
        float wy1 = ys - y0f, wx1 = xsm - x0f;
        float wy0 = 1.f - wy1, wx0 = 1.f - wx1;
        bool vy0 = (y0f >= 0.f) && (y0f <= 63.f);
        bool vy1 = (y1f >= 0.f) && (y1f <= 63.f);
        bool vx0 = (x0f >= 0.f) && (x0f <= 63.f);
        bool vx1 = (x1f >= 0.f) && (x1f <= 63.f);
        cw00[tid] = (vy0 && vx0) ? wy0 * wx0 : 0.f;
        cw01[tid] = (vy0 && vx1) ? wy0 * wx1 : 0.f;
        cw10[tid] = (vy1 && vx0) ? wy1 * wx0 : 0.f;
        cw11[tid] = (vy1 && vx1) ? wy1 * wx1 : 0.f;
        int y0c = (int)fminf(fmaxf(y0f, 0.f), 63.f);
        int x0c = (int)fminf(fmaxf(x0f, 0.f), 63.f);
        int y1c = (int)fminf(fmaxf(y1f, 0.f), 63.f);
        int x1c = (int)fminf(fmaxf(x1f, 0.f), 63.f);
        cpos[tid] = y0c | (x0c << 6) | (y1c << 12) | (x1c << 18);
    }
    __syncthreads();

    // bilinear gather into SMEM columns
    for (int t = tid; t < 9216; t += 256) {
        int px = t & 15, c = (t >> 4) & 63, k = t >> 10;
        int pair = k * 16 + px;
        int p  = cpos[pair];
        int y0 = p & 63, x0 = (p >> 6) & 63;
        int y1 = (p >> 12) & 63, x1 = (p >> 18) & 63;
        const float* xb = x + (b * 64 + c) * HW;
        float v = cw00[pair] * xb[y0 * 64 + x0]
                + cw01[pair] * xb[y0 * 64 + x1]
                + cw10[pair] * xb[y1 * 64 + x0]
                + cw11[pair] * xb[y1 * 64 + x1];
        val[(k * 64 + c) * 16 + px] = v;
    }

    // GEMM: out[64][16] = w1t[64][576] * val[576][16]  (packed f32x2)
    ull acc01 = 0ull, acc23 = 0ull;
    int ty = tid >> 4, tx = tid & 15;
    for (int j = 0; j < 18; j++) {
        __syncthreads();
        for (int i = tid; i < 2048; i += 256)
            wsh[i] = g_w1t[j * 2048 + i];
        __syncthreads();
#pragma unroll 8
        for (int kcl = 0; kcl < 32; kcl++) {
            const float2* wp = (const float2*)&wsh[kcl * 64 + ty * 4];
            float2 w01 = wp[0], w23 = wp[1];
            float  xv  = val[(j * 32 + kcl) * 16 + tx];
            ull xp = pack2(xv, xv);
            ffma2(acc01, pack2(w01.x, w01.y), xp);
            ffma2(acc23, pack2(w23.x, w23.y), xp);
        }
    }
    int wo = wo0 + tx;
    float2 a01 = unpack2(acc01), a23 = unpack2(acc23);
    float a[4] = {a01.x, a01.y, a23.x, a23.y};
#pragma unroll
    for (int m = 0; m < 4; m++) {
        int oc = ty * 4 + m;
        float r = fmaxf(a[m] * scale[oc] + bias[oc], 0.f);
        g_s[((b * 64 + oc) * 64 + ho) * 64 + wo] = r;
    }
}

// ---------------------------------------------------------------------------
// Kernels 4/5: tiled direct conv w/ packed f32x2 inner loop
// MODE 0: g_s += relu(bn(conv_KSZ(x)))           (5x5 branch)
// MODE 1: dst  = relu(bn(conv_KSZ(g_s)) + resid) (final 3x3 + identity)
// ---------------------------------------------------------------------------
template <int KSZ, int MODE>
__global__ __launch_bounds__(256, 2) void conv_tiled_kernel(
    const float* __restrict__ src, const float* __restrict__ w,
    const float* __restrict__ gg, const float* __restrict__ bbn,
    const float* __restrict__ mmn, const float* __restrict__ vvn,
    const float* __restrict__ resid, float* __restrict__ dst)
{
    constexpr int PAD = KSZ / 2;
    constexpr int XH  = 16 + KSZ - 1;
    constexpr int XW  = XH;
    // even stride with gcd(XWP,32)==2 => conflict-free LDS.64 across rows
    constexpr int XWP = (XW % 4 == 0) ? XW + 2 : XW;
    constexpr int KK  = KSZ * KSZ;
    constexpr int NP  = XW / 2;          // even-parity pairs
    constexpr int NPO = NP - 1;          // odd-parity pairs

    __shared__ float xs[4][XH][XWP];
    __shared__ float wsm[4 * KK][64];
    __shared__ float scale[64], bias[64];

    int tid = threadIdx.x;
    int b   = blockIdx.y;
    int ty0 = (blockIdx.x >> 2) * 16;
    int tx0 = (blockIdx.x & 3) * 16;
    int ty  = tid >> 4, tx = tid & 15;

    if (tid < 64) {
        float sc   = gg[tid] * rsqrtf(vvn[tid] + 1e-5f);
        scale[tid] = sc;
        bias[tid]  = bbn[tid] - mmn[tid] * sc;
    }

    const float* in = (MODE == 0) ? src : (const float*)g_s;

    // accp[m][j] accumulates output cols n=2j (lo), n=2j+1 (hi)
    ull accp[4][8];
#pragma unroll
    for (int m = 0; m < 4; m++)
#pragma unroll
        for (int j = 0; j < 8; j++) accp[m][j] = 0ull;

    for (int cc0 = 0; cc0 < 64; cc0 += 4) {
        __syncthreads();
        for (int i = tid; i < 4 * XH * XW; i += 256) {
            int c = i / (XH * XW), r = i % (XH * XW), yy = r / XW, xx = r % XW;
            int gy = ty0 - PAD + yy, gx = tx0 - PAD + xx;
            float v = 0.f;
            if (gy >= 0 && gy < 64 && gx >= 0 && gx < 64)
                v = in[((b * 64 + cc0 + c) * 64 + gy) * 64 + gx];
            xs[c][yy][xx] = v;
        }
        for (int i = tid; i < 64 * 4 * KK; i += 256) {
            int o = i / (4 * KK), r = i % (4 * KK), c = r / KK, kk = r % KK;
            wsm[c * KK + kk][o] = w[(o * 64 + cc0 + c) * KK + kk];
        }
        __syncthreads();
#pragma unroll
        for (int c = 0; c < 4; c++)
#pragma unroll
        for (int ky = 0; ky < KSZ; ky++) {
            const float* xr = &xs[c][tx + ky][0];
            float2 f[NP];
#pragma unroll
            for (int i2 = 0; i2 < NP; i2++)
                f[i2] = *(const float2*)(xr + 2 * i2);   // aligned LDS.64
            ull ep[NP], op[NPO];
#pragma unroll
            for (int i2 = 0; i2 < NP; i2++)  ep[i2] = pack2(f[i2].x, f[i2].y);
#pragma unroll
            for (int i2 = 0; i2 < NPO; i2++) op[i2] = pack2(f[i2].y, f[i2 + 1].x);
#pragma unroll
            for (int kx = 0; kx < KSZ; kx++) {
                float4 wv = *(const float4*)&wsm[c * KK + ky * KSZ + kx][ty * 4];
                ull w0 = pack2(wv.x, wv.x), w1 = pack2(wv.y, wv.y);
                ull w2 = pack2(wv.z, wv.z), w3 = pack2(wv.w, wv.w);
                const ull* xp = (kx & 1) ? &op[kx >> 1] : &ep[kx >> 1];
#pragma unroll
                for (int j = 0; j < 8; j++) {
                    ull xv = xp[j];
                    ffma2(accp[0][j], w0, xv);
                    ffma2(accp[1][j], w1, xv);
                    ffma2(accp[2][j], w2, xv);
                    ffma2(accp[3][j], w3, xv);
                }
            }
        }
    }

    int row = ty0 + tx;
#pragma unroll
    for (int m = 0; m < 4; m++) {
        int oc   = ty * 4 + m;
        int base = ((b * 64 + oc) * 64 + row) * 64 + tx0;
        float sc = scale[oc], bi = bias[oc];
#pragma unroll
        for (int j = 0; j < 8; j++) {
            float2 a = unpack2(accp[m][j]);
            float r0 = a.x * sc + bi;
            float r1 = a.y * sc + bi;
            if (MODE == 0) {
                g_s[base + 2 * j]     = fmaxf(r0, 0.f) + g_s[base + 2 * j];
                g_s[base + 2 * j + 1] = fmaxf(r1, 0.f) + g_s[base + 2 * j + 1];
            } else {
                dst[base + 2 * j]     = fmaxf(r0 + resid[base + 2 * j], 0.f);
                dst[base + 2 * j + 1] = fmaxf(r1 + resid[base + 2 * j + 1], 0.f);
            }
        }
    }
}

// ---------------------------------------------------------------------------
extern "C" void kernel_launch(void* const* d_in, const int* in_sizes, int n_in,
                              void* d_out, int out_size)
{
    const float* x     = (const float*)d_in[0];
    const float* w_off = (const float*)d_in[1];
    const float* b_off = (const float*)d_in[2];
    const float* w1    = (const float*)d_in[3];
    const float* g1    = (const float*)d_in[4];
    const float* b1    = (const float*)d_in[5];
    const float* m1    = (const float*)d_in[6];
    const float* v1    = (const float*)d_in[7];
    const float* w3    = (const float*)d_in[8];
    const float* g3    = (const float*)d_in[9];
    const float* b3    = (const float*)d_in[10];
    const float* m3    = (const float*)d_in[11];
    const float* v3    = (const float*)d_in[12];
    const float* w2    = (const float*)d_in[13];
    const float* g2    = (const float*)d_in[14];
    const float* b2    = (const float*)d_in[15];
    const float* m2    = (const float*)d_in[16];
    const float* v2    = (const float*)d_in[17];
    float* out = (float*)d_out;

    offset_conv_kernel<<<dim3(16, 16), 256>>>(x, w_off, b_off);
    repack_w1_kernel<<<144, 256>>>(w1);
    deform_kernel<<<dim3(4, 64, 16), 256>>>(x, g1, b1, m1, v1);
    conv_tiled_kernel<5, 0><<<dim3(16, 16), 256>>>(x, w3, g3, b3, m3, v3,
                                                   nullptr, nullptr);
    conv_tiled_kernel<3, 1><<<dim3(16, 16), 256>>>(nullptr, w2, g2, b2, m2, v2,
                                                   x, out);
}

// round 4
// speedup vs baseline: 1.0351x; 1.0348x over previous
#include <cuda_runtime.h>

#define BB 16
#define CC 64
#define HH 64
#define WW 64
#define HW 4096

typedef unsigned long long ull;

__device__ float g_off[BB * 18 * HW];      // offsets from offset conv
__device__ float g_s[BB * CC * HW];        // branch-sum feature map
__device__ float g_w1t[576 * 64];          // w1 repacked: [k*64+c][o]

// ---- f32x2 packed helpers ------------------------------------------------
__device__ __forceinline__ void ffma2(ull& d, ull a, ull b) {
    asm("fma.rn.f32x2 %0, %1, %2, %0;" : "+l"(d) : "l"(a), "l"(b));
}
__device__ __forceinline__ ull pack2(float lo, float hi) {
    ull r;
    asm("mov.b64 %0, {%1, %2};" : "=l"(r) : "f"(lo), "f"(hi));
    return r;
}
__device__ __forceinline__ float2 unpack2(ull v) {
    float2 r;
    asm("mov.b64 {%0, %1}, %2;" : "=f"(r.x), "=f"(r.y) : "l"(v));
    return r;
}

// ---------------------------------------------------------------------------
// Kernel 1: offset conv — 3x3, pad 1, Cin=64, Cout=18, plus bias
// ws[tap][18]: oc-pairs are adjacent -> direct LDS.64, no packing
// ---------------------------------------------------------------------------
__global__ __launch_bounds__(256) void offset_conv_kernel(
    const float* __restrict__ x, const float* __restrict__ w_off,
    const float* __restrict__ b_off)
{
    __shared__ float ws[576 * 18];        // 41.5 KB, [tap][o]
    __shared__ float xs[4][18][19];

    int tid = threadIdx.x;
    int b   = blockIdx.y;
    int ty0 = (blockIdx.x >> 2) * 16;
    int tx0 = (blockIdx.x & 3) * 16;
    int ty  = tid >> 4, tx = tid & 15;

    for (int i = tid; i < 576 * 18; i += 256) {
        int tap = i / 18, o = i % 18;
        ws[i] = w_off[o * 576 + tap];
    }

    ull accp[9];
#pragma unroll
    for (int j = 0; j < 9; j++) accp[j] = 0ull;

    for (int cc0 = 0; cc0 < 64; cc0 += 4) {
        __syncthreads();
        for (int i = tid; i < 4 * 18 * 18; i += 256) {
            int c = i / 324, r = i % 324, yy = r / 18, xx = r % 18;
            int gy = ty0 - 1 + yy, gx = tx0 - 1 + xx;
            float v = 0.f;
            if (gy >= 0 && gy < 64 && gx >= 0 && gx < 64)
                v = x[((b * 64 + cc0 + c) * 64 + gy) * 64 + gx];
            xs[c][yy][xx] = v;
        }
        __syncthreads();
#pragma unroll
        for (int c = 0; c < 4; c++)
#pragma unroll
        for (int ky = 0; ky < 3; ky++)
#pragma unroll
        for (int kx = 0; kx < 3; kx++) {
            float xv = xs[c][ty + ky][tx + kx];
            ull xp = pack2(xv, xv);
            const ull* wp =
                (const ull*)&ws[(((cc0 + c) * 3 + ky) * 3 + kx) * 18];
#pragma unroll
            for (int j = 0; j < 9; j++)
                ffma2(accp[j], wp[j], xp);
        }
    }
    int ho = ty0 + ty, wo = tx0 + tx;
#pragma unroll
    for (int j = 0; j < 9; j++) {
        float2 a = unpack2(accp[j]);
        g_off[((b * 18 + 2 * j) * 64 + ho) * 64 + wo]     = a.x + b_off[2 * j];
        g_off[((b * 18 + 2 * j + 1) * 64 + ho) * 64 + wo] = a.y + b_off[2 * j + 1];
    }
}

// ---------------------------------------------------------------------------
// Kernel 2: repack w1 [o][c][3][3] -> g_w1t[(k*64+c)*64 + o]
// ---------------------------------------------------------------------------
__global__ void repack_w1_kernel(const float* __restrict__ w1)
{
    int i = blockIdx.x * 256 + threadIdx.x;
    if (i < 36864) {
        int o = i / 576, r = i % 576, c = r / 9, k = r % 9;
        g_w1t[(k * 64 + c) * 64 + o] = w1[i];
    }
}

// ---------------------------------------------------------------------------
// Kernel 3: fused deformable conv (3x3, pad 1) + BN1 + ReLU -> g_s
// ---------------------------------------------------------------------------
__global__ __launch_bounds__(256) void deform_kernel(
    const float* __restrict__ x,
    const float* __restrict__ g1, const float* __restrict__ b1,
    const float* __restrict__ m1, const float* __restrict__ v1)
{
    __shared__ float val[576 * 16];
    __shared__ float wsh[32 * 64];
    __shared__ int   cpos[144];
    __shared__ float cw00[144], cw01[144], cw10[144], cw11[144];
    __shared__ float scale[64], bias[64];

    int tid = threadIdx.x;
    int wo0 = blockIdx.x * 16;
    int ho  = blockIdx.y;
    int b   = blockIdx.z;

    if (tid < 64) {
        float sc   = g1[tid] * rsqrtf(v1[tid] + 1e-5f);
        scale[tid] = sc;
        bias[tid]  = b1[tid] - m1[tid] * sc;
    }
    if (tid < 144) {
        int k = tid / 16, px = tid & 15;
        int ky = k / 3, kx = k % 3;
        int wo = wo0 + px;
        float dy = g_off[((b * 18 + 2 * k) * 64 + ho) * 64 + wo];
        float dx = g_off[((b * 18 + 2 * k + 1) * 64 + ho) * 64 + wo];
        float ys  = (float)(ho - 1 + ky) + dy;
        float xsm = (float)(wo - 1 + kx) + dx;
        float y0f = floorf(ys), x0f = floorf(xsm);
        float y1f = y0f + 1.f, x1f = x0f + 1.f;
        float wy1 = ys - y0f, wx1 = xsm - x0f;
        float wy0 = 1.f - wy1, wx0 = 1.f - wx1;
        bool vy0 = (y0f >= 0.f) && (y0f <= 63.f);
        bool vy1 = (y1f >= 0.f) && (y1f <= 63.f);
        bool vx0 = (x0f >= 0.f) && (x0f <= 63.f);
        bool vx1 = (x1f >= 0.f) && (x1f <= 63.f);
        cw00[tid] = (vy0 && vx0) ? wy0 * wx0 : 0.f;
        cw01[tid] = (vy0 && vx1) ? wy0 * wx1 : 0.f;
        cw10[tid] = (vy1 && vx0) ? wy1 * wx0 : 0.f;
        cw11[tid] = (vy1 && vx1) ? wy1 * wx1 : 0.f;
        int y0c = (int)fminf(fmaxf(y0f, 0.f), 63.f);
        int x0c = (int)fminf(fmaxf(x0f, 0.f), 63.f);
        int y1c = (int)fminf(fmaxf(y1f, 0.f), 63.f);
        int x1c = (int)fminf(fmaxf(x1f, 0.f), 63.f);
        cpos[tid] = y0c | (x0c << 6) | (y1c << 12) | (x1c << 18);
    }
    __syncthreads();

    for (int t = tid; t < 9216; t += 256) {
        int px = t & 15, c = (t >> 4) & 63, k = t >> 10;
        int pair = k * 16 + px;
        int p  = cpos[pair];
        int y0 = p & 63, x0 = (p >> 6) & 63;
        int y1 = (p >> 12) & 63, x1 = (p >> 18) & 63;
        const float* xb = x + (b * 64 + c) * HW;
        float v = cw00[pair] * xb[y0 * 64 + x0]
                + cw01[pair] * xb[y0 * 64 + x1]
                + cw10[pair] * xb[y1 * 64 + x0]
                + cw11[pair] * xb[y1 * 64 + x1];
        val[(k * 64 + c) * 16 + px] = v;
    }

    // GEMM: out[64][16] = w1t[64][576] * val[576][16]
    ull acc01 = 0ull, acc23 = 0ull;
    int ty = tid >> 4, tx = tid & 15;
    for (int j = 0; j < 18; j++) {
        __syncthreads();
        for (int i = tid; i < 2048; i += 256)
            wsh[i] = g_w1t[j * 2048 + i];
        __syncthreads();
#pragma unroll 8
        for (int kcl = 0; kcl < 32; kcl++) {
            const ull* wp = (const ull*)&wsh[kcl * 64 + ty * 4];
            float  xv  = val[(j * 32 + kcl) * 16 + tx];
            ull xp = pack2(xv, xv);
            ffma2(acc01, wp[0], xp);
            ffma2(acc23, wp[1], xp);
        }
    }
    int wo = wo0 + tx;
    float2 a01 = unpack2(acc01), a23 = unpack2(acc23);
    float a[4] = {a01.x, a01.y, a23.x, a23.y};
#pragma unroll
    for (int m = 0; m < 4; m++) {
        int oc = ty * 4 + m;
        float r = fmaxf(a[m] * scale[oc] + bias[oc], 0.f);
        g_s[((b * 64 + oc) * 64 + ho) * 64 + wo] = r;
    }
}

// ---------------------------------------------------------------------------
// Kernels 4/5: tiled conv, f32x2 with ZERO in-loop packing.
// wdup: weights duplicated -> LDS.128 gives 2 broadcast pairs.
// xsA: normal tile (even pairs via LDS.64); xsB: shifted by 1 (odd pairs).
// MODE 0: g_s += relu(bn(conv_KSZ(x)));  MODE 1: dst = relu(bn(conv(g_s))+resid)
// ---------------------------------------------------------------------------
template <int KSZ, int MODE>
__global__ __launch_bounds__(256, 2) void conv_tiled_kernel(
    const float* __restrict__ src, const float* __restrict__ w,
    const float* __restrict__ gg, const float* __restrict__ bbn,
    const float* __restrict__ mmn, const float* __restrict__ vvn,
    const float* __restrict__ resid, float* __restrict__ dst)
{
    constexpr int PAD = KSZ / 2;
    constexpr int XH  = 16 + KSZ - 1;
    constexpr int XW  = XH;
    constexpr int XWP = (XW % 4 == 0) ? XW + 2 : XW;  // even, gcd(.,32)=2
    constexpr int KK  = KSZ * KSZ;
    constexpr int NP  = XW / 2;

    extern __shared__ float sm[];
    float* xsA   = sm;                        // [4][XH][XWP]
    float* xsB   = xsA + 4 * XH * XWP;        // [4][XH][XWP] shifted +1
    float* wdup  = xsB + 4 * XH * XWP;        // [4*KK][128] duplicated
    float* scale = wdup + 4 * KK * 128;
    float* bias  = scale + 64;

    int tid = threadIdx.x;
    int b   = blockIdx.y;
    int ty0 = (blockIdx.x >> 2) * 16;
    int tx0 = (blockIdx.x & 3) * 16;
    int ty  = tid >> 4, tx = tid & 15;

    if (tid < 64) {
        float sc   = gg[tid] * rsqrtf(vvn[tid] + 1e-5f);
        scale[tid] = sc;
        bias[tid]  = bbn[tid] - mmn[tid] * sc;
    }

    const float* in = (MODE == 0) ? src : (const float*)g_s;

    ull accp[4][8];
#pragma unroll
    for (int m = 0; m < 4; m++)
#pragma unroll
        for (int j = 0; j < 8; j++) accp[m][j] = 0ull;

    for (int cc0 = 0; cc0 < 64; cc0 += 4) {
        __syncthreads();
        for (int i = tid; i < 4 * XH * XW; i += 256) {
            int c = i / (XH * XW), r = i % (XH * XW), yy = r / XW, xx = r % XW;
            int gy = ty0 - PAD + yy, gx = tx0 - PAD + xx;
            const float* inb = in + ((b * 64 + cc0 + c) * 64) * 64;
            float vA = 0.f, vB = 0.f;
            if (gy >= 0 && gy < 64) {
                if (gx >= 0 && gx < 64)      vA = inb[gy * 64 + gx];
                if (gx + 1 >= 0 && gx + 1 < 64) vB = inb[gy * 64 + gx + 1];
            }
            xsA[(c * XH + yy) * XWP + xx] = vA;
            xsB[(c * XH + yy) * XWP + xx] = vB;
        }
        for (int i = tid; i < 64 * 4 * KK; i += 256) {
            int o = i / (4 * KK), r = i % (4 * KK), c = r / KK, kk = r % KK;
            float v = w[(o * 64 + cc0 + c) * KK + kk];
            wdup[(c * KK + kk) * 128 + 2 * o]     = v;
            wdup[(c * KK + kk) * 128 + 2 * o + 1] = v;
        }
        __syncthreads();
#pragma unroll
        for (int c = 0; c < 4; c++)
#pragma unroll
        for (int ky = 0; ky < KSZ; ky++) {
            const float* rowA = xsA + (c * XH + tx + ky) * XWP;
            const float* rowB = xsB + (c * XH + tx + ky) * XWP;
            ull ep[NP];
#pragma unroll
            for (int i2 = 0; i2 < NP; i2++)
                ep[i2] = *(const ull*)(rowA + 2 * i2);
#pragma unroll
            for (int kx = 0; kx < KSZ; kx++) {
                const ulonglong2* wp = (const ulonglong2*)
                    (wdup + (c * KK + ky * KSZ + kx) * 128 + ty * 8);
                ulonglong2 wab = wp[0];   // (o0,o0),(o1,o1)
                ulonglong2 wcd = wp[1];   // (o2,o2),(o3,o3)
                if ((kx & 1) == 0) {
                    int t = kx >> 1;
#pragma unroll
                    for (int j = 0; j < 8; j++) {
                        ull xv = ep[j + t];
                        ffma2(accp[0][j], wab.x, xv);
                        ffma2(accp[1][j], wab.y, xv);
                        ffma2(accp[2][j], wcd.x, xv);
                        ffma2(accp[3][j], wcd.y, xv);
                    }
                } else {
                    int t = kx >> 1;
#pragma unroll
                    for (int j = 0; j < 8; j++) {
                        ull xv = *(const ull*)(rowB + 2 * (j + t));
                        ffma2(accp[0][j], wab.x, xv);
                        ffma2(accp[1][j], wab.y, xv);
                        ffma2(accp[2][j], wcd.x, xv);
                        ffma2(accp[3][j], wcd.y, xv);
                    }
                }
            }
        }
    }

    int row = ty0 + tx;
#pragma unroll
    for (int m = 0; m < 4; m++) {
        int oc   = ty * 4 + m;
        int base = ((b * 64 + oc) * 64 + row) * 64 + tx0;
        float sc = scale[oc], bi = bias[oc];
#pragma unroll
        for (int j = 0; j < 8; j++) {
            float2 a = unpack2(accp[m][j]);
            float r0 = a.x * sc + bi;
            float r1 = a.y * sc + bi;
            if (MODE == 0) {
                g_s[base + 2 * j]     = fmaxf(r0, 0.f) + g_s[base + 2 * j];
                g_s[base + 2 * j + 1] = fmaxf(r1, 0.f) + g_s[base + 2 * j + 1];
            } else {
                dst[base + 2 * j]     = fmaxf(r0 + resid[base + 2 * j], 0.f);
                dst[base + 2 * j + 1] = fmaxf(r1 + resid[base + 2 * j + 1], 0.f);
            }
        }
    }
}

// ---------------------------------------------------------------------------
extern "C" void kernel_launch(void* const* d_in, const int* in_sizes, int n_in,
                              void* d_out, int out_size)
{
    const float* x     = (const float*)d_in[0];
    const float* w_off = (const float*)d_in[1];
    const float* b_off = (const float*)d_in[2];
    const float* w1    = (const float*)d_in[3];
    const float* g1    = (const float*)d_in[4];
    const float* b1    = (const float*)d_in[5];
    const float* m1    = (const float*)d_in[6];
    const float* v1    = (const float*)d_in[7];
    const float* w3    = (const float*)d_in[8];
    const float* g3    = (const float*)d_in[9];
    const float* b3    = (const float*)d_in[10];
    const float* m3    = (const float*)d_in[11];
    const float* v3    = (const float*)d_in[12];
    const float* w2    = (const float*)d_in[13];
    const float* g2    = (const float*)d_in[14];
    const float* b2    = (const float*)d_in[15];
    const float* m2    = (const float*)d_in[16];
    const float* v2    = (const float*)d_in[17];
    float* out = (float*)d_out;

    // dynamic smem sizes
    const int smem5 = (2 * 4 * 20 * 22 + 4 * 25 * 128 + 128) * 4;  // 65,792
    const int smem3 = (2 * 4 * 18 * 18 + 4 * 9 * 128 + 128) * 4;   // 29,312
    static bool attr_set = false;
    if (!attr_set) {
        cudaFuncSetAttribute(conv_tiled_kernel<5, 0>,
                             cudaFuncAttributeMaxDynamicSharedMemorySize, smem5);
        cudaFuncSetAttribute(conv_tiled_kernel<3, 1>,
                             cudaFuncAttributeMaxDynamicSharedMemorySize, smem3);
        attr_set = true;
    }

    offset_conv_kernel<<<dim3(16, 16), 256>>>(x, w_off, b_off);
    repack_w1_kernel<<<144, 256>>>(w1);
    deform_kernel<<<dim3(4, 64, 16), 256>>>(x, g1, b1, m1, v1);
    conv_tiled_kernel<5, 0><<<dim3(16, 16), 256, smem5>>>(x, w3, g3, b3, m3, v3,
                                                          nullptr, nullptr);
    conv_tiled_kernel<3, 1><<<dim3(16, 16), 256, smem3>>>(nullptr, w2, g2, b2,
                                                          m2, v2, x, out);
}